// round 3
// baseline (speedup 1.0000x reference)
#include <cuda_runtime.h>

// RotationGate: batched RX on qubit 0 (MSB axis) of a 22-qubit state.
// state_re/state_im: (DIM, 16) fp32 row-major; each row = 4 float4.
// out: (2, DIM, 16) fp32 (real plane, imag plane).
// Pair (j, j+DIM/2):
//   out0 = c*s0 - i*s*s1 ; out1 = c*s1 - i*s*s0  with c=cos(th/2), s=sin(th/2)
// HBM-bound streaming (1.07 GB). Fused single kernel: per-block sincos into
// smem hidden under the bulk global loads. Plain cached loads/stores (R2
// showed .cs hints cost ~3us / 1.4% DRAM util).

#define DIM_    4194304L
#define BATCH_  16L
#define HALF4   ((DIM_ / 2) * BATCH_ / 4)   /* 8,388,608 float4 per half-plane */
#define IMOFF   (DIM_ * BATCH_ / 4)         /* 16,777,216 float4: imag plane  */

__global__ __launch_bounds__(256, 8)
void rot_fused_kernel(const float* __restrict__ theta,
                      const float* __restrict__ re_,
                      const float* __restrict__ im_,
                      float* __restrict__ out_) {
    __shared__ __align__(16) float sc[16];
    __shared__ __align__(16) float ss[16];

    long t = (long)blockIdx.x * 256L + threadIdx.x;   // t in [0, HALF4)
    const float4* __restrict__ re  = (const float4*)re_;
    const float4* __restrict__ im  = (const float4*)im_;
    float4* __restrict__ out = (float4*)out_;

    // Theta load first (tiny, broadcast), then the four bulk loads so all
    // long-latency memory is in flight before any dependent work.
    float a = 0.0f;
    if (threadIdx.x < 16) a = theta[threadIdx.x] * 0.5f;

    float4 r0 = re[t];
    float4 i0 = im[t];
    float4 r1 = re[t + HALF4];
    float4 i1 = im[t + HALF4];

    if (threadIdx.x < 16) {
        sc[threadIdx.x] = cosf(a);
        ss[threadIdx.x] = sinf(a);
    }
    __syncthreads();

    int g = (int)(t & 3);  // batch quad: batches 4g..4g+3
    float4 c4 = ((const float4*)sc)[g];
    float4 s4 = ((const float4*)ss)[g];

    float4 o0r, o0i, o1r, o1i;

    o0r.x = fmaf(c4.x, r0.x,  s4.x * i1.x);
    o0r.y = fmaf(c4.y, r0.y,  s4.y * i1.y);
    o0r.z = fmaf(c4.z, r0.z,  s4.z * i1.z);
    o0r.w = fmaf(c4.w, r0.w,  s4.w * i1.w);

    o0i.x = fmaf(c4.x, i0.x, -s4.x * r1.x);
    o0i.y = fmaf(c4.y, i0.y, -s4.y * r1.y);
    o0i.z = fmaf(c4.z, i0.z, -s4.z * r1.z);
    o0i.w = fmaf(c4.w, i0.w, -s4.w * r1.w);

    o1r.x = fmaf(c4.x, r1.x,  s4.x * i0.x);
    o1r.y = fmaf(c4.y, r1.y,  s4.y * i0.y);
    o1r.z = fmaf(c4.z, r1.z,  s4.z * i0.z);
    o1r.w = fmaf(c4.w, r1.w,  s4.w * i0.w);

    o1i.x = fmaf(c4.x, i1.x, -s4.x * r0.x);
    o1i.y = fmaf(c4.y, i1.y, -s4.y * r0.y);
    o1i.z = fmaf(c4.z, i1.z, -s4.z * r0.z);
    o1i.w = fmaf(c4.w, i1.w, -s4.w * r0.w);

    out[t]                 = o0r;
    out[t + HALF4]         = o1r;
    out[t + IMOFF]         = o0i;
    out[t + IMOFF + HALF4] = o1i;
}

extern "C" void kernel_launch(void* const* d_in, const int* in_sizes, int n_in,
                              void* d_out, int out_size) {
    const float* theta = (const float*)d_in[0];
    const float* s_re  = (const float*)d_in[1];
    const float* s_im  = (const float*)d_in[2];
    float* out = (float*)d_out;

    long total  = HALF4;          // 8,388,608 threads
    int  tpb    = 256;
    long blocks = total / tpb;    // 32,768 blocks
    rot_fused_kernel<<<(unsigned)blocks, tpb>>>(theta, s_re, s_im, out);
}

// round 4
// speedup vs baseline: 1.0150x; 1.0150x over previous
#include <cuda_runtime.h>

// RotationGate: batched RX on qubit 0 (MSB axis) of a 22-qubit state.
// state_re/state_im: (DIM, 16) fp32 row-major; each row = 4 float4.
// out: (2, DIM, 16) fp32 (real plane, imag plane).
// Pair (j, j+DIM/2):
//   out0 = c*s0 - i*s*s1 ; out1 = c*s1 - i*s*s0  with c=cos(th/2), s=sin(th/2)
//
// HBM-bound streaming (1.07 GB). Lessons from R1-R3:
//  - separate prep kernel: best main-kernel stream (152.8us) but +7.5us node gap
//  - fused with __syncthreads: barrier gates stores on warp0 -> main +3..5us
// R4: fused with ZERO sync. Every thread computes its own 4 (c,s) pairs via
// MUFU intrinsics (theta/2 in [0,pi], abs err ~1e-6 << 1e-3 tolerance).
// One broadcast float4 theta load per thread; no smem, no branch, no barrier.

#define DIM_    4194304L
#define BATCH_  16L
#define HALF4   ((DIM_ / 2) * BATCH_ / 4)   /* 8,388,608 float4 per half-plane */
#define IMOFF   (DIM_ * BATCH_ / 4)         /* 16,777,216 float4: imag plane  */

__global__ __launch_bounds__(256, 8)
void rot_fused_kernel(const float* __restrict__ theta,
                      const float* __restrict__ re_,
                      const float* __restrict__ im_,
                      float* __restrict__ out_) {
    long t = (long)blockIdx.x * 256L + threadIdx.x;   // t in [0, HALF4)
    const float4* __restrict__ re  = (const float4*)re_;
    const float4* __restrict__ im  = (const float4*)im_;
    float4* __restrict__ out = (float4*)out_;

    int g = (int)(threadIdx.x & 3);  // batch quad: batches 4g..4g+3

    // Broadcast 16B theta load (L2/L1 hit after first touch) issued alongside
    // the bulk loads; MUFU work overlaps the DRAM latency.
    float4 th = ((const float4*)theta)[g];

    float4 r0 = re[t];
    float4 i0 = im[t];
    float4 r1 = re[t + HALF4];
    float4 i1 = im[t + HALF4];

    float4 c4, s4;
    c4.x = __cosf(th.x * 0.5f);  s4.x = __sinf(th.x * 0.5f);
    c4.y = __cosf(th.y * 0.5f);  s4.y = __sinf(th.y * 0.5f);
    c4.z = __cosf(th.z * 0.5f);  s4.z = __sinf(th.z * 0.5f);
    c4.w = __cosf(th.w * 0.5f);  s4.w = __sinf(th.w * 0.5f);

    float4 o0r, o0i, o1r, o1i;

    o0r.x = fmaf(c4.x, r0.x,  s4.x * i1.x);
    o0r.y = fmaf(c4.y, r0.y,  s4.y * i1.y);
    o0r.z = fmaf(c4.z, r0.z,  s4.z * i1.z);
    o0r.w = fmaf(c4.w, r0.w,  s4.w * i1.w);

    o0i.x = fmaf(c4.x, i0.x, -s4.x * r1.x);
    o0i.y = fmaf(c4.y, i0.y, -s4.y * r1.y);
    o0i.z = fmaf(c4.z, i0.z, -s4.z * r1.z);
    o0i.w = fmaf(c4.w, i0.w, -s4.w * r1.w);

    o1r.x = fmaf(c4.x, r1.x,  s4.x * i0.x);
    o1r.y = fmaf(c4.y, r1.y,  s4.y * i0.y);
    o1r.z = fmaf(c4.z, r1.z,  s4.z * i0.z);
    o1r.w = fmaf(c4.w, r1.w,  s4.w * i0.w);

    o1i.x = fmaf(c4.x, i1.x, -s4.x * r0.x);
    o1i.y = fmaf(c4.y, i1.y, -s4.y * r0.y);
    o1i.z = fmaf(c4.z, i1.z, -s4.z * r0.z);
    o1i.w = fmaf(c4.w, i1.w, -s4.w * r0.w);

    out[t]                 = o0r;
    out[t + HALF4]         = o1r;
    out[t + IMOFF]         = o0i;
    out[t + IMOFF + HALF4] = o1i;
}

extern "C" void kernel_launch(void* const* d_in, const int* in_sizes, int n_in,
                              void* d_out, int out_size) {
    const float* theta = (const float*)d_in[0];
    const float* s_re  = (const float*)d_in[1];
    const float* s_im  = (const float*)d_in[2];
    float* out = (float*)d_out;

    long total  = HALF4;          // 8,388,608 threads
    int  tpb    = 256;
    long blocks = total / tpb;    // 32,768 blocks
    rot_fused_kernel<<<(unsigned)blocks, tpb>>>(theta, s_re, s_im, out);
}